// round 15
// baseline (speedup 1.0000x reference)
#include <cuda_runtime.h>
#include <cuda_bf16.h>
#include <math.h>
#include <float.h>
#include <stdint.h>

// Problem constants
#define DDIM 256
#define KCODE 1024
#define HW 4096
#define NPOS 65536
#define ZQ_ELEMS 16777216

// Screening margin: dv_approx and dv_ref both lie on the ulp(~256)=3.05e-5
// grid; pre-rounding difference 2*eps_c ~ 3e-6 << ulp/2 => each rounds to
// within 1 grid point. gap > 2*ulp + slack => argmin provably identical.
#define DELTA_GAP 6.5e-5f

__device__ float  g_b[KCODE];
__device__ float  g_a[NPOS];
__device__ int    g_idx[NPOS];
__device__ int    g_flag[NPOS];
__device__ int    g_cnt;
__device__ double g_loss;
__device__ __align__(16) __nv_bfloat16 g_eh[KCODE * DDIM];
__device__ __align__(16) __nv_bfloat16 g_el[KCODE * DDIM];
__device__ __align__(16) float g_zf[(size_t)NPOS * DDIM / 8];
__device__ float g_pm1[16 * NPOS];
__device__ int   g_pk1[16 * NPOS];

// ---------------------------------------------------------------------------
// PTX helpers — all sm_80-class features, valid on plain sm_103 target
// ---------------------------------------------------------------------------
__device__ __forceinline__ unsigned stu32(const void* p) {
    return (unsigned)__cvta_generic_to_shared(p);
}
__device__ __forceinline__ void cp16(unsigned dst, const void* src) {
    asm volatile("cp.async.cg.shared.global [%0], [%1], 16;" :: "r"(dst), "l"(src));
}
__device__ __forceinline__ void cp_commit() { asm volatile("cp.async.commit_group;"); }
__device__ __forceinline__ void cp_wait1()  { asm volatile("cp.async.wait_group 1;"); }
__device__ __forceinline__ void cp_wait0()  { asm volatile("cp.async.wait_group 0;"); }

__device__ __forceinline__ void ldm4(unsigned* r, unsigned addr) {
    asm volatile("ldmatrix.sync.aligned.m8n8.x4.shared.b16 {%0,%1,%2,%3}, [%4];"
        : "=r"(r[0]), "=r"(r[1]), "=r"(r[2]), "=r"(r[3]) : "r"(addr));
}
__device__ __forceinline__ void mma16816(float* c, const unsigned* a,
                                         unsigned b0, unsigned b1) {
    asm volatile(
        "mma.sync.aligned.m16n8k16.row.col.f32.bf16.bf16.f32 "
        "{%0,%1,%2,%3}, {%4,%5,%6,%7}, {%8,%9}, {%0,%1,%2,%3};"
        : "+f"(c[0]), "+f"(c[1]), "+f"(c[2]), "+f"(c[3])
        : "r"(a[0]), "r"(a[1]), "r"(a[2]), "r"(a[3]), "r"(b0), "r"(b1));
}

// ---------------------------------------------------------------------------
// emb prep (unchanged, proven)
// ---------------------------------------------------------------------------
__global__ void k_prep(const float* __restrict__ emb) {
    if (blockIdx.x == 0 && threadIdx.x == 0) { g_loss = 0.0; g_cnt = 0; }
    int warp = blockIdx.x * (blockDim.x >> 5) + (threadIdx.x >> 5);
    int lane = threadIdx.x & 31;
    if (warp >= KCODE) return;
    const float* row = emb + (size_t)warp * DDIM;
    float s = 0.f;
    #pragma unroll
    for (int d = lane; d < DDIM; d += 32) { float v = row[d]; s = fmaf(v, v, s); }
    #pragma unroll
    for (int o = 16; o; o >>= 1) s += __shfl_xor_sync(0xffffffffu, s, o);
    if (lane == 0) g_b[warp] = s;

    __align__(16) __nv_bfloat16 h[8], l[8];
    int base = lane * 8;
    #pragma unroll
    for (int q = 0; q < 8; ++q) {
        float v = row[base + q];
        h[q] = __float2bfloat16(v);
        l[q] = __float2bfloat16(v - __bfloat162float(h[q]));
    }
    *reinterpret_cast<uint4*>(&g_eh[warp * DDIM + base]) = *reinterpret_cast<uint4*>(h);
    *reinterpret_cast<uint4*>(&g_el[warp * DDIM + base]) = *reinterpret_cast<uint4*>(l);
}

__global__ void k_nop() {}

// ---------------------------------------------------------------------------
// HMMA screening kernel (R8/R12 structure; 12 DISTINCT accumulator tiles:
// Ch = zh*eh, Cle = zh*el, Cla = zl*eh — each touched once per s-iter so
// the accumulator RAW distance is 12 MMA issues, hiding HMMA latency).
// 256 threads, CTA = 128 n x all 1024 codes.
// ---------------------------------------------------------------------------
#define ROWB 528
#define OFF_AH 0
#define OFF_AL 67584            /* 128*528 */
#define OFF_B  135168           /* 2 bufs x (Bh 16896 + Bl 16896); also z stage */
#define OFF_BS 202752           /* 1024 floats */
#define OFF_AS 206848           /* 128 floats */
#define SM_TOTAL 207360
#define PSTG 132

extern __shared__ char sm_raw[];

__global__ void __launch_bounds__(256, 1)
k_mma(const float* __restrict__ z) {
    unsigned sb = stu32(sm_raw);
    const int tid = threadIdx.x;
    const int lane = tid & 31, w = tid >> 5;         // w = n-tile 0..7
    const int n0 = blockIdx.x * 128;

    // ---------- Prologue: stage z (fp32) -> split into Ah/Al + exact a_n ----
    float* stg = (float*)(sm_raw + OFF_B);
    const int b = n0 >> 12, hw0 = n0 & 4095;
    const float* zb = z + ((size_t)b << 20) + hw0;
    float a_acc = 0.f;

    #pragma unroll
    for (int c = 0; c < 2; ++c) {
        for (int i = tid; i < 128 * 32; i += 256) {
            int d = i >> 5, j = i & 31;
            cp16(sb + OFF_B + d * ROWB + j * 16,
                 zb + (size_t)(c * 128 + d) * HW + j * 4);
        }
        cp_commit(); cp_wait0();
        __syncthreads();
        {
            int nn = tid >> 1, hf = tid & 1;
            unsigned dstA = (unsigned)(nn * ROWB + c * 256 + hf * 128);
            #pragma unroll
            for (int g = 0; g < 8; ++g) {
                __align__(16) __nv_bfloat16 hh[8], ll[8];
                #pragma unroll
                for (int q = 0; q < 8; ++q) {
                    float v = stg[(hf * 64 + g * 8 + q) * PSTG + nn];
                    hh[q] = __float2bfloat16(v);
                    ll[q] = __float2bfloat16(v - __bfloat162float(hh[q]));
                }
                *(uint4*)(sm_raw + OFF_AH + dstA + g * 16) = *(uint4*)hh;
                *(uint4*)(sm_raw + OFF_AL + dstA + g * 16) = *(uint4*)ll;
            }
        }
        if (tid < 128) {
            #pragma unroll 4
            for (int dl = 0; dl < 128; ++dl) {
                float v = stg[dl * PSTG + tid];
                a_acc = fmaf(v, v, a_acc);
            }
        }
        __syncthreads();
    }

    float* bsm  = (float*)(sm_raw + OFF_BS);
    float* asm_ = (float*)(sm_raw + OFF_AS);
    if (tid < 128) { asm_[tid] = a_acc; g_a[n0 + tid] = a_acc; }
    for (int i = tid; i < KCODE; i += 256) bsm[i] = g_b[i];

    auto prefB = [&](int c) {
        unsigned bufh = sb + OFF_B + (c & 1) * 33792;
        const char* eh = (const char*)g_eh;
        const char* el = (const char*)g_el;
        for (int u = tid; u < 32 * 32; u += 256) {
            int r = u >> 5, j = u & 31;
            size_t src = (size_t)(c * 32 + r) * 512 + j * 16;
            unsigned dst = r * ROWB + j * 16;
            cp16(bufh + dst, eh + src);
            cp16(bufh + 16896 + dst, el + src);
        }
    };
    prefB(0); cp_commit();
    prefB(1); cp_commit();
    __syncthreads();

    const int grp = lane >> 3, ii = lane & 7;
    const unsigned aOff = (unsigned)((w * 16 + ((grp & 1) ? 8 : 0) + ii) * ROWB
                                     + ((grp & 2) ? 16 : 0));
    const unsigned bOff = (unsigned)((((grp >> 1) ? 8 : 0) + ii) * ROWB
                                     + ((grp & 1) ? 16 : 0));

    const float aA = asm_[w * 16 + (lane >> 2)];
    const float aB = asm_[w * 16 + (lane >> 2) + 8];
    float m1A = FLT_MAX, m2A = FLT_MAX, m1B = FLT_MAX, m2B = FLT_MAX;
    int k1A = 0, k1B = 0;

    #define UPD(m1, m2, k1, dv, k) \
        { if ((dv) < (m1)) { (m2) = (m1); (m1) = (dv); (k1) = (k); } \
          else if ((dv) < (m2)) (m2) = (dv); }

    for (int c = 0; c < 32; ++c) {
        if (c == 31) cp_wait0(); else cp_wait1();
        __syncthreads();

        unsigned bufh = sb + OFF_B + (c & 1) * 33792;
        unsigned pAh = sb + OFF_AH + aOff;
        unsigned pAl = sb + OFF_AL + aOff;
        unsigned pH0 = bufh + bOff;
        unsigned pH1 = bufh + 16 * ROWB + bOff;
        unsigned pL0 = bufh + 16896 + bOff;
        unsigned pL1 = bufh + 16896 + 16 * ROWB + bOff;

        // 12 distinct accumulator tiles: no tile written twice per s-iter.
        float Ch[4][4], Cle[4][4], Cla[4][4];
        #pragma unroll
        for (int t = 0; t < 4; ++t)
            #pragma unroll
            for (int q = 0; q < 4; ++q) { Ch[t][q] = 0.f; Cle[t][q] = 0.f; Cla[t][q] = 0.f; }

        #pragma unroll 4
        for (int s = 0; s < 16; ++s) {
            unsigned Ah[4], Al[4], B0[4], B1[4], B2[4], B3[4];
            ldm4(Ah, pAh); ldm4(Al, pAl);
            ldm4(B0, pH0); ldm4(B1, pH1);
            ldm4(B2, pL0); ldm4(B3, pL1);
            mma16816(Cle[0], Ah, B2[0], B2[1]);   // zh*el
            mma16816(Cle[1], Ah, B2[2], B2[3]);
            mma16816(Cle[2], Ah, B3[0], B3[1]);
            mma16816(Cle[3], Ah, B3[2], B3[3]);
            mma16816(Ch[0], Ah, B0[0], B0[1]);    // zh*eh
            mma16816(Ch[1], Ah, B0[2], B0[3]);
            mma16816(Ch[2], Ah, B1[0], B1[1]);
            mma16816(Ch[3], Ah, B1[2], B1[3]);
            mma16816(Cla[0], Al, B0[0], B0[1]);   // zl*eh
            mma16816(Cla[1], Al, B0[2], B0[3]);
            mma16816(Cla[2], Al, B1[0], B1[1]);
            mma16816(Cla[3], Al, B1[2], B1[3]);
            pAh += 32; pAl += 32; pH0 += 32; pH1 += 32; pL0 += 32; pL1 += 32;
        }

        int kb = c * 32 + (lane & 3) * 2;
        #pragma unroll
        for (int t = 0; t < 4; ++t) {
            int kc = kb + t * 8;
            float b0 = bsm[kc], b1 = bsm[kc + 1];
            float c00 = Ch[t][0] + (Cle[t][0] + Cla[t][0]);
            float c01 = Ch[t][1] + (Cle[t][1] + Cla[t][1]);
            float c10 = Ch[t][2] + (Cle[t][2] + Cla[t][2]);
            float c11 = Ch[t][3] + (Cle[t][3] + Cla[t][3]);
            float d0 = fmaf(-2.f, c00, aA + b0);
            float d1 = fmaf(-2.f, c01, aA + b1);
            float d2 = fmaf(-2.f, c10, aB + b0);
            float d3 = fmaf(-2.f, c11, aB + b1);
            UPD(m1A, m2A, k1A, d0, kc);
            UPD(m1A, m2A, k1A, d1, kc + 1);
            UPD(m1B, m2B, k1B, d2, kc);
            UPD(m1B, m2B, k1B, d3, kc + 1);
        }

        __syncthreads();
        if (c + 2 < 32) { prefB(c + 2); cp_commit(); }
    }

    #pragma unroll
    for (int o = 1; o <= 2; o <<= 1) {
        float om1 = __shfl_xor_sync(0xffffffffu, m1A, o);
        int   ok1 = __shfl_xor_sync(0xffffffffu, k1A, o);
        float om2 = __shfl_xor_sync(0xffffffffu, m2A, o);
        bool take = (om1 < m1A) || (om1 == m1A && ok1 < k1A);
        m2A = fminf(fminf(m2A, om2), take ? m1A : om1);
        if (take) { m1A = om1; k1A = ok1; }

        om1 = __shfl_xor_sync(0xffffffffu, m1B, o);
        ok1 = __shfl_xor_sync(0xffffffffu, k1B, o);
        om2 = __shfl_xor_sync(0xffffffffu, m2B, o);
        take = (om1 < m1B) || (om1 == m1B && ok1 < k1B);
        m2B = fminf(fminf(m2B, om2), take ? m1B : om1);
        if (take) { m1B = om1; k1B = ok1; }
    }
    if ((lane & 3) == 0) {
        int nA = n0 + w * 16 + (lane >> 2);
        if (m2A - m1A > DELTA_GAP) g_idx[nA] = k1A;
        else g_flag[atomicAdd(&g_cnt, 1)] = nA;
        int nB = nA + 8;
        if (m2B - m1B > DELTA_GAP) g_idx[nB] = k1B;
        else g_flag[atomicAdd(&g_cnt, 1)] = nB;
    }
}

// ---------------------------------------------------------------------------
// One-shot z gather (R12, proven)
// ---------------------------------------------------------------------------
__global__ void k_gz(const float* __restrict__ z) {
    int cnt = g_cnt;
    int wg = blockIdx.x * (blockDim.x >> 5) + (threadIdx.x >> 5);
    int lane = threadIdx.x & 31;
    for (int s = wg; s < cnt; s += gridDim.x * (blockDim.x >> 5)) {
        int n = g_flag[s];
        const float* zp = z + ((size_t)(n >> 12) << 20) + (n & 4095);
        float* dst = g_zf + (size_t)s * DDIM;
        #pragma unroll
        for (int j = 0; j < 8; ++j) {
            int d = lane + 32 * j;
            dst[d] = __ldg(zp + ((size_t)d << 12));
        }
    }
}

// ---------------------------------------------------------------------------
// Exact fallback stage 1 (R14, proven): 4-position register blocking.
// ---------------------------------------------------------------------------
#define EXP 260
#define SMEX ((64 * EXP + 32 * EXP) * 4)

extern __shared__ float exs[];

__global__ __launch_bounds__(256)
void k_ex1(const float* __restrict__ emb) {
    float* es = exs;                     // [64][EXP]
    float* zs = exs + 64 * EXP;          // [32][EXP]
    __shared__ int ns[32];
    __shared__ float aa[32];
    int tx = threadIdx.x & 31, ty = threadIdx.x >> 5;
    const int cy = blockIdx.y, c0 = cy * 64;
    const int cnt = g_cnt;
    if (cnt == 0) return;

    for (int i = threadIdx.x; i < 64 * 64; i += 256) {
        int r = i >> 6, q = (i & 63) << 2;
        *(float4*)(es + r * EXP + q) =
            *(const float4*)(emb + (size_t)(c0 + r) * DDIM + q);
    }
    float bk0 = g_b[c0 + tx], bk1 = g_b[c0 + 32 + tx];
    __syncthreads();

    for (int base = blockIdx.x * 32; base < cnt; base += 32 * 32) {
        if (threadIdx.x < 32) {
            int v = (base + threadIdx.x < cnt) ? g_flag[base + threadIdx.x] : -1;
            ns[threadIdx.x] = v;
            aa[threadIdx.x] = (v >= 0) ? g_a[v] : 0.f;
        }
        __syncthreads();
        for (int i = threadIdx.x; i < 32 * 64; i += 256) {
            int sl = i >> 6, q = (i & 63) << 2;
            float4 v = (base + sl < cnt)
                ? *(const float4*)(g_zf + (size_t)(base + sl) * DDIM + q)
                : make_float4(0.f, 0.f, 0.f, 0.f);
            *(float4*)(zs + sl * EXP + q) = v;
        }
        __syncthreads();

        float ca[4] = {0.f, 0.f, 0.f, 0.f}, cb[4] = {0.f, 0.f, 0.f, 0.f};
        const float* zr0 = zs + (ty * 4 + 0) * EXP;
        const float* zr1 = zs + (ty * 4 + 1) * EXP;
        const float* zr2 = zs + (ty * 4 + 2) * EXP;
        const float* zr3 = zs + (ty * 4 + 3) * EXP;
        const float* e0 = es + tx * EXP;
        const float* e1 = es + (tx + 32) * EXP;
        #pragma unroll 4
        for (int q = 0; q < 64; ++q) {
            float4 u = *(const float4*)(e0 + 4 * q);
            float4 v = *(const float4*)(e1 + 4 * q);
            float4 z0 = *(const float4*)(zr0 + 4 * q);
            float4 z1 = *(const float4*)(zr1 + 4 * q);
            float4 z2 = *(const float4*)(zr2 + 4 * q);
            float4 z3 = *(const float4*)(zr3 + 4 * q);
            ca[0]=fmaf(z0.x,u.x,ca[0]); ca[0]=fmaf(z0.y,u.y,ca[0]);
            ca[0]=fmaf(z0.z,u.z,ca[0]); ca[0]=fmaf(z0.w,u.w,ca[0]);
            cb[0]=fmaf(z0.x,v.x,cb[0]); cb[0]=fmaf(z0.y,v.y,cb[0]);
            cb[0]=fmaf(z0.z,v.z,cb[0]); cb[0]=fmaf(z0.w,v.w,cb[0]);
            ca[1]=fmaf(z1.x,u.x,ca[1]); ca[1]=fmaf(z1.y,u.y,ca[1]);
            ca[1]=fmaf(z1.z,u.z,ca[1]); ca[1]=fmaf(z1.w,u.w,ca[1]);
            cb[1]=fmaf(z1.x,v.x,cb[1]); cb[1]=fmaf(z1.y,v.y,cb[1]);
            cb[1]=fmaf(z1.z,v.z,cb[1]); cb[1]=fmaf(z1.w,v.w,cb[1]);
            ca[2]=fmaf(z2.x,u.x,ca[2]); ca[2]=fmaf(z2.y,u.y,ca[2]);
            ca[2]=fmaf(z2.z,u.z,ca[2]); ca[2]=fmaf(z2.w,u.w,ca[2]);
            cb[2]=fmaf(z2.x,v.x,cb[2]); cb[2]=fmaf(z2.y,v.y,cb[2]);
            cb[2]=fmaf(z2.z,v.z,cb[2]); cb[2]=fmaf(z2.w,v.w,cb[2]);
            ca[3]=fmaf(z3.x,u.x,ca[3]); ca[3]=fmaf(z3.y,u.y,ca[3]);
            ca[3]=fmaf(z3.z,u.z,ca[3]); ca[3]=fmaf(z3.w,u.w,ca[3]);
            cb[3]=fmaf(z3.x,v.x,cb[3]); cb[3]=fmaf(z3.y,v.y,cb[3]);
            cb[3]=fmaf(z3.z,v.z,cb[3]); cb[3]=fmaf(z3.w,v.w,cb[3]);
        }
        #pragma unroll
        for (int p = 0; p < 4; ++p) {
            int slot = ty * 4 + p;
            float a = aa[slot];
            float dv0 = fmaf(-2.0f, ca[p], a + bk0);
            float dv1 = fmaf(-2.0f, cb[p], a + bk1);
            float m1 = dv0; int k1 = c0 + tx;
            if (dv1 < m1) { m1 = dv1; k1 = c0 + 32 + tx; }
            #pragma unroll
            for (int o = 16; o; o >>= 1) {
                float ov = __shfl_xor_sync(0xffffffffu, m1, o);
                int   ok = __shfl_xor_sync(0xffffffffu, k1, o);
                if (ov < m1 || (ov == m1 && ok < k1)) { m1 = ov; k1 = ok; }
            }
            if (tx == 0 && ns[slot] >= 0) {
                g_pm1[cy * NPOS + base + slot] = m1;
                g_pk1[cy * NPOS + base + slot] = k1;
            }
        }
        __syncthreads();
    }
}

__global__ void k_ex2() {
    int i = blockIdx.x * blockDim.x + threadIdx.x;
    if (i >= g_cnt) return;
    float m = FLT_MAX; int k = 0;
    #pragma unroll
    for (int cy = 0; cy < 16; ++cy) {
        float mm = g_pm1[cy * NPOS + i];
        int   kk = g_pk1[cy * NPOS + i];
        if (mm < m || (mm == m && kk < k)) { m = mm; k = kk; }
    }
    g_idx[g_flag[i]] = k;
}

// ---------------------------------------------------------------------------
// Output + loss (proven in R3)
// ---------------------------------------------------------------------------
__global__ void k_out(const float* __restrict__ z, const float* __restrict__ emb,
                      float* __restrict__ out) {
    const int nitems = NPOS * 64;
    float local = 0.f;
    for (int item = blockIdx.x * blockDim.x + threadIdx.x;
         item < nitems; item += gridDim.x * blockDim.x) {
        int n  = item & (NPOS - 1);
        int dq = item >> 16;
        int idx = __ldg(&g_idx[n]);
        float4 e4 = *(const float4*)(emb + (size_t)idx * DDIM + (dq << 2));
        int b = n >> 12, hw = n & 4095;
        size_t base = ((size_t)b << 20) + ((size_t)(dq << 2) << 12) + hw;
        float ev[4] = {e4.x, e4.y, e4.z, e4.w};
        #pragma unroll
        for (int q = 0; q < 4; ++q) {
            size_t a = base + ((size_t)q << 12);
            float zz = z[a];
            float diff = ev[q] - zz;
            out[a] = zz + diff;
            local = fmaf(diff, diff, local);
        }
    }
    #pragma unroll
    for (int o = 16; o; o >>= 1) local += __shfl_xor_sync(0xffffffffu, local, o);
    __shared__ float ws[32];
    int lane = threadIdx.x & 31, w = threadIdx.x >> 5;
    if (lane == 0) ws[w] = local;
    __syncthreads();
    if (w == 0) {
        float s = (lane < (int)(blockDim.x >> 5)) ? ws[lane] : 0.f;
        #pragma unroll
        for (int o = 16; o; o >>= 1) s += __shfl_xor_sync(0xffffffffu, s, o);
        if (lane == 0) atomicAdd(&g_loss, (double)s);
    }
}

__global__ void k_fin(float* __restrict__ out, long long out_size) {
    int i = blockIdx.x * blockDim.x + threadIdx.x;
    if (i < NPOS && (long long)ZQ_ELEMS + i < out_size)
        out[ZQ_ELEMS + i] = (float)g_idx[i];
    if (i == 0 && (long long)ZQ_ELEMS + NPOS < out_size)
        out[ZQ_ELEMS + NPOS] = (float)(0.25 * g_loss / (double)ZQ_ELEMS);
}

// ---------------------------------------------------------------------------
extern "C" void kernel_launch(void* const* d_in, const int* in_sizes, int n_in,
                              void* d_out, int out_size) {
    const float* z   = (const float*)d_in[0];
    const float* emb = (const float*)d_in[1];
    float* out = (float*)d_out;

    cudaFuncSetAttribute(k_mma, cudaFuncAttributeMaxDynamicSharedMemorySize, SM_TOTAL);
    cudaFuncSetAttribute(k_ex1, cudaFuncAttributeMaxDynamicSharedMemorySize, SMEX);

    k_prep<<<KCODE / 8, 256>>>(emb);
    k_nop<<<1, 32>>>();
    k_nop<<<1, 32>>>();
    k_mma<<<NPOS / 128, 256, SM_TOTAL>>>(z);   // capture slot #4 = k_mma
    k_gz<<<256, 256>>>(z);
    k_ex1<<<dim3(32, 16), 256, SMEX>>>(emb);
    k_ex2<<<NPOS / 256, 256>>>();
    k_out<<<2048, 256>>>(z, emb, out);
    k_fin<<<(NPOS + 255) / 256, 256>>>(out, (long long)out_size);
}

// round 16
// speedup vs baseline: 1.0254x; 1.0254x over previous
#include <cuda_runtime.h>
#include <cuda_bf16.h>
#include <math.h>
#include <float.h>
#include <stdint.h>

// Problem constants
#define DDIM 256
#define KCODE 1024
#define HW 4096
#define NPOS 65536
#define ZQ_ELEMS 16777216

// Screening margin: dv_approx and dv_ref both lie on the ulp(~256)=3.05e-5
// grid; pre-rounding difference 2*eps_c ~ 3e-6 << ulp/2 => each rounds to
// within 1 grid point. gap > 2*ulp + slack => argmin provably identical.
#define DELTA_GAP 6.5e-5f

__device__ float  g_b[KCODE];
__device__ float  g_a[NPOS];
__device__ int    g_idx[NPOS];
__device__ int    g_flag[NPOS];
__device__ int    g_cnt;
__device__ double g_loss;
__device__ __align__(16) __nv_bfloat16 g_eh[KCODE * DDIM];
__device__ __align__(16) __nv_bfloat16 g_el[KCODE * DDIM];
__device__ __align__(16) float g_zf[(size_t)NPOS * DDIM / 8];
__device__ float g_pm1[16 * NPOS];
__device__ int   g_pk1[16 * NPOS];

// ---------------------------------------------------------------------------
// PTX helpers — all sm_80-class features, valid on plain sm_103 target
// ---------------------------------------------------------------------------
__device__ __forceinline__ unsigned stu32(const void* p) {
    return (unsigned)__cvta_generic_to_shared(p);
}
__device__ __forceinline__ void cp16(unsigned dst, const void* src) {
    asm volatile("cp.async.cg.shared.global [%0], [%1], 16;" :: "r"(dst), "l"(src));
}
__device__ __forceinline__ void cp_commit() { asm volatile("cp.async.commit_group;"); }
__device__ __forceinline__ void cp_wait1()  { asm volatile("cp.async.wait_group 1;"); }
__device__ __forceinline__ void cp_wait0()  { asm volatile("cp.async.wait_group 0;"); }

__device__ __forceinline__ void ldm4(unsigned* r, unsigned addr) {
    asm volatile("ldmatrix.sync.aligned.m8n8.x4.shared.b16 {%0,%1,%2,%3}, [%4];"
        : "=r"(r[0]), "=r"(r[1]), "=r"(r[2]), "=r"(r[3]) : "r"(addr));
}
__device__ __forceinline__ void mma16816(float* c, const unsigned* a,
                                         unsigned b0, unsigned b1) {
    asm volatile(
        "mma.sync.aligned.m16n8k16.row.col.f32.bf16.bf16.f32 "
        "{%0,%1,%2,%3}, {%4,%5,%6,%7}, {%8,%9}, {%0,%1,%2,%3};"
        : "+f"(c[0]), "+f"(c[1]), "+f"(c[2]), "+f"(c[3])
        : "r"(a[0]), "r"(a[1]), "r"(a[2]), "r"(a[3]), "r"(b0), "r"(b1));
}

// ---------------------------------------------------------------------------
// emb prep (unchanged, proven)
// ---------------------------------------------------------------------------
__global__ void k_prep(const float* __restrict__ emb) {
    if (blockIdx.x == 0 && threadIdx.x == 0) { g_loss = 0.0; g_cnt = 0; }
    int warp = blockIdx.x * (blockDim.x >> 5) + (threadIdx.x >> 5);
    int lane = threadIdx.x & 31;
    if (warp >= KCODE) return;
    const float* row = emb + (size_t)warp * DDIM;
    float s = 0.f;
    #pragma unroll
    for (int d = lane; d < DDIM; d += 32) { float v = row[d]; s = fmaf(v, v, s); }
    #pragma unroll
    for (int o = 16; o; o >>= 1) s += __shfl_xor_sync(0xffffffffu, s, o);
    if (lane == 0) g_b[warp] = s;

    __align__(16) __nv_bfloat16 h[8], l[8];
    int base = lane * 8;
    #pragma unroll
    for (int q = 0; q < 8; ++q) {
        float v = row[base + q];
        h[q] = __float2bfloat16(v);
        l[q] = __float2bfloat16(v - __bfloat162float(h[q]));
    }
    *reinterpret_cast<uint4*>(&g_eh[warp * DDIM + base]) = *reinterpret_cast<uint4*>(h);
    *reinterpret_cast<uint4*>(&g_el[warp * DDIM + base]) = *reinterpret_cast<uint4*>(l);
}

// ---------------------------------------------------------------------------
// HMMA screening kernel (exact R14/R8 structure, proven 410us config;
// only change: s-loop unroll 4 -> 8 for deeper LDSM/MMA interleaving).
// 256 threads, CTA = 128 n x all 1024 codes.
// ---------------------------------------------------------------------------
#define ROWB 528
#define OFF_AH 0
#define OFF_AL 67584            /* 128*528 */
#define OFF_B  135168           /* 2 bufs x (Bh 16896 + Bl 16896); also z stage */
#define OFF_BS 202752           /* 1024 floats */
#define OFF_AS 206848           /* 128 floats */
#define SM_TOTAL 207360
#define PSTG 132

extern __shared__ char sm_raw[];

__global__ void __launch_bounds__(256, 1)
k_mma(const float* __restrict__ z) {
    unsigned sb = stu32(sm_raw);
    const int tid = threadIdx.x;
    const int lane = tid & 31, w = tid >> 5;         // w = n-tile 0..7
    const int n0 = blockIdx.x * 128;

    // ---------- Prologue: stage z (fp32) -> split into Ah/Al + exact a_n ----
    float* stg = (float*)(sm_raw + OFF_B);
    const int b = n0 >> 12, hw0 = n0 & 4095;
    const float* zb = z + ((size_t)b << 20) + hw0;
    float a_acc = 0.f;

    #pragma unroll
    for (int c = 0; c < 2; ++c) {
        for (int i = tid; i < 128 * 32; i += 256) {
            int d = i >> 5, j = i & 31;
            cp16(sb + OFF_B + d * ROWB + j * 16,
                 zb + (size_t)(c * 128 + d) * HW + j * 4);
        }
        cp_commit(); cp_wait0();
        __syncthreads();
        {
            int nn = tid >> 1, hf = tid & 1;
            unsigned dstA = (unsigned)(nn * ROWB + c * 256 + hf * 128);
            #pragma unroll
            for (int g = 0; g < 8; ++g) {
                __align__(16) __nv_bfloat16 hh[8], ll[8];
                #pragma unroll
                for (int q = 0; q < 8; ++q) {
                    float v = stg[(hf * 64 + g * 8 + q) * PSTG + nn];
                    hh[q] = __float2bfloat16(v);
                    ll[q] = __float2bfloat16(v - __bfloat162float(hh[q]));
                }
                *(uint4*)(sm_raw + OFF_AH + dstA + g * 16) = *(uint4*)hh;
                *(uint4*)(sm_raw + OFF_AL + dstA + g * 16) = *(uint4*)ll;
            }
        }
        if (tid < 128) {
            #pragma unroll 4
            for (int dl = 0; dl < 128; ++dl) {
                float v = stg[dl * PSTG + tid];
                a_acc = fmaf(v, v, a_acc);
            }
        }
        __syncthreads();
    }

    float* bsm  = (float*)(sm_raw + OFF_BS);
    float* asm_ = (float*)(sm_raw + OFF_AS);
    if (tid < 128) { asm_[tid] = a_acc; g_a[n0 + tid] = a_acc; }
    for (int i = tid; i < KCODE; i += 256) bsm[i] = g_b[i];

    auto prefB = [&](int c) {
        unsigned bufh = sb + OFF_B + (c & 1) * 33792;
        const char* eh = (const char*)g_eh;
        const char* el = (const char*)g_el;
        for (int u = tid; u < 32 * 32; u += 256) {
            int r = u >> 5, j = u & 31;
            size_t src = (size_t)(c * 32 + r) * 512 + j * 16;
            unsigned dst = r * ROWB + j * 16;
            cp16(bufh + dst, eh + src);
            cp16(bufh + 16896 + dst, el + src);
        }
    };
    prefB(0); cp_commit();
    prefB(1); cp_commit();
    __syncthreads();

    const int grp = lane >> 3, ii = lane & 7;
    const unsigned aOff = (unsigned)((w * 16 + ((grp & 1) ? 8 : 0) + ii) * ROWB
                                     + ((grp & 2) ? 16 : 0));
    const unsigned bOff = (unsigned)((((grp >> 1) ? 8 : 0) + ii) * ROWB
                                     + ((grp & 1) ? 16 : 0));

    const float aA = asm_[w * 16 + (lane >> 2)];
    const float aB = asm_[w * 16 + (lane >> 2) + 8];
    float m1A = FLT_MAX, m2A = FLT_MAX, m1B = FLT_MAX, m2B = FLT_MAX;
    int k1A = 0, k1B = 0;

    #define UPD(m1, m2, k1, dv, k) \
        { if ((dv) < (m1)) { (m2) = (m1); (m1) = (dv); (k1) = (k); } \
          else if ((dv) < (m2)) (m2) = (dv); }

    for (int c = 0; c < 32; ++c) {
        if (c == 31) cp_wait0(); else cp_wait1();
        __syncthreads();

        unsigned bufh = sb + OFF_B + (c & 1) * 33792;
        unsigned pAh = sb + OFF_AH + aOff;
        unsigned pAl = sb + OFF_AL + aOff;
        unsigned pH0 = bufh + bOff;
        unsigned pH1 = bufh + 16 * ROWB + bOff;
        unsigned pL0 = bufh + 16896 + bOff;
        unsigned pL1 = bufh + 16896 + 16 * ROWB + bOff;

        float Ch[4][4], Cl[4][4];
        #pragma unroll
        for (int t = 0; t < 4; ++t)
            #pragma unroll
            for (int q = 0; q < 4; ++q) { Ch[t][q] = 0.f; Cl[t][q] = 0.f; }

        #pragma unroll 8
        for (int s = 0; s < 16; ++s) {
            unsigned Ah[4], Al[4], B0[4], B1[4], B2[4], B3[4];
            ldm4(Ah, pAh); ldm4(Al, pAl);
            ldm4(B0, pH0); ldm4(B1, pH1);
            ldm4(B2, pL0); ldm4(B3, pL1);
            mma16816(Cl[0], Ah, B2[0], B2[1]);   // zh*el
            mma16816(Cl[1], Ah, B2[2], B2[3]);
            mma16816(Cl[2], Ah, B3[0], B3[1]);
            mma16816(Cl[3], Ah, B3[2], B3[3]);
            mma16816(Ch[0], Ah, B0[0], B0[1]);   // zh*eh
            mma16816(Ch[1], Ah, B0[2], B0[3]);
            mma16816(Ch[2], Ah, B1[0], B1[1]);
            mma16816(Ch[3], Ah, B1[2], B1[3]);
            mma16816(Cl[0], Al, B0[0], B0[1]);   // zl*eh
            mma16816(Cl[1], Al, B0[2], B0[3]);
            mma16816(Cl[2], Al, B1[0], B1[1]);
            mma16816(Cl[3], Al, B1[2], B1[3]);
            pAh += 32; pAl += 32; pH0 += 32; pH1 += 32; pL0 += 32; pL1 += 32;
        }

        int kb = c * 32 + (lane & 3) * 2;
        #pragma unroll
        for (int t = 0; t < 4; ++t) {
            int kc = kb + t * 8;
            float b0 = bsm[kc], b1 = bsm[kc + 1];
            float d0 = fmaf(-2.f, Ch[t][0] + Cl[t][0], aA + b0);
            float d1 = fmaf(-2.f, Ch[t][1] + Cl[t][1], aA + b1);
            float d2 = fmaf(-2.f, Ch[t][2] + Cl[t][2], aB + b0);
            float d3 = fmaf(-2.f, Ch[t][3] + Cl[t][3], aB + b1);
            UPD(m1A, m2A, k1A, d0, kc);
            UPD(m1A, m2A, k1A, d1, kc + 1);
            UPD(m1B, m2B, k1B, d2, kc);
            UPD(m1B, m2B, k1B, d3, kc + 1);
        }

        __syncthreads();
        if (c + 2 < 32) { prefB(c + 2); cp_commit(); }
    }

    #pragma unroll
    for (int o = 1; o <= 2; o <<= 1) {
        float om1 = __shfl_xor_sync(0xffffffffu, m1A, o);
        int   ok1 = __shfl_xor_sync(0xffffffffu, k1A, o);
        float om2 = __shfl_xor_sync(0xffffffffu, m2A, o);
        bool take = (om1 < m1A) || (om1 == m1A && ok1 < k1A);
        m2A = fminf(fminf(m2A, om2), take ? m1A : om1);
        if (take) { m1A = om1; k1A = ok1; }

        om1 = __shfl_xor_sync(0xffffffffu, m1B, o);
        ok1 = __shfl_xor_sync(0xffffffffu, k1B, o);
        om2 = __shfl_xor_sync(0xffffffffu, m2B, o);
        take = (om1 < m1B) || (om1 == m1B && ok1 < k1B);
        m2B = fminf(fminf(m2B, om2), take ? m1B : om1);
        if (take) { m1B = om1; k1B = ok1; }
    }
    if ((lane & 3) == 0) {
        int nA = n0 + w * 16 + (lane >> 2);
        if (m2A - m1A > DELTA_GAP) g_idx[nA] = k1A;
        else g_flag[atomicAdd(&g_cnt, 1)] = nA;
        int nB = nA + 8;
        if (m2B - m1B > DELTA_GAP) g_idx[nB] = k1B;
        else g_flag[atomicAdd(&g_cnt, 1)] = nB;
    }
}

// ---------------------------------------------------------------------------
// One-shot z gather (R12, proven)
// ---------------------------------------------------------------------------
__global__ void k_gz(const float* __restrict__ z) {
    int cnt = g_cnt;
    int wg = blockIdx.x * (blockDim.x >> 5) + (threadIdx.x >> 5);
    int lane = threadIdx.x & 31;
    for (int s = wg; s < cnt; s += gridDim.x * (blockDim.x >> 5)) {
        int n = g_flag[s];
        const float* zp = z + ((size_t)(n >> 12) << 20) + (n & 4095);
        float* dst = g_zf + (size_t)s * DDIM;
        #pragma unroll
        for (int j = 0; j < 8; ++j) {
            int d = lane + 32 * j;
            dst[d] = __ldg(zp + ((size_t)d << 12));
        }
    }
}

// ---------------------------------------------------------------------------
// Exact fallback stage 1 (R14, proven): 4-position register blocking.
// Grid widened to (64,16) for more CTA parallelism at typical counts.
// ---------------------------------------------------------------------------
#define EXP 260
#define SMEX ((64 * EXP + 32 * EXP) * 4)

extern __shared__ float exs[];

__global__ __launch_bounds__(256)
void k_ex1(const float* __restrict__ emb) {
    float* es = exs;                     // [64][EXP]
    float* zs = exs + 64 * EXP;          // [32][EXP]
    __shared__ int ns[32];
    __shared__ float aa[32];
    int tx = threadIdx.x & 31, ty = threadIdx.x >> 5;
    const int cy = blockIdx.y, c0 = cy * 64;
    const int cnt = g_cnt;
    if (cnt == 0) return;

    for (int i = threadIdx.x; i < 64 * 64; i += 256) {
        int r = i >> 6, q = (i & 63) << 2;
        *(float4*)(es + r * EXP + q) =
            *(const float4*)(emb + (size_t)(c0 + r) * DDIM + q);
    }
    float bk0 = g_b[c0 + tx], bk1 = g_b[c0 + 32 + tx];
    __syncthreads();

    for (int base = blockIdx.x * 32; base < cnt; base += 64 * 32) {
        if (threadIdx.x < 32) {
            int v = (base + threadIdx.x < cnt) ? g_flag[base + threadIdx.x] : -1;
            ns[threadIdx.x] = v;
            aa[threadIdx.x] = (v >= 0) ? g_a[v] : 0.f;
        }
        __syncthreads();
        for (int i = threadIdx.x; i < 32 * 64; i += 256) {
            int sl = i >> 6, q = (i & 63) << 2;
            float4 v = (base + sl < cnt)
                ? *(const float4*)(g_zf + (size_t)(base + sl) * DDIM + q)
                : make_float4(0.f, 0.f, 0.f, 0.f);
            *(float4*)(zs + sl * EXP + q) = v;
        }
        __syncthreads();

        float ca[4] = {0.f, 0.f, 0.f, 0.f}, cb[4] = {0.f, 0.f, 0.f, 0.f};
        const float* zr0 = zs + (ty * 4 + 0) * EXP;
        const float* zr1 = zs + (ty * 4 + 1) * EXP;
        const float* zr2 = zs + (ty * 4 + 2) * EXP;
        const float* zr3 = zs + (ty * 4 + 3) * EXP;
        const float* e0 = es + tx * EXP;
        const float* e1 = es + (tx + 32) * EXP;
        #pragma unroll 4
        for (int q = 0; q < 64; ++q) {
            float4 u = *(const float4*)(e0 + 4 * q);
            float4 v = *(const float4*)(e1 + 4 * q);
            float4 z0 = *(const float4*)(zr0 + 4 * q);
            float4 z1 = *(const float4*)(zr1 + 4 * q);
            float4 z2 = *(const float4*)(zr2 + 4 * q);
            float4 z3 = *(const float4*)(zr3 + 4 * q);
            ca[0]=fmaf(z0.x,u.x,ca[0]); ca[0]=fmaf(z0.y,u.y,ca[0]);
            ca[0]=fmaf(z0.z,u.z,ca[0]); ca[0]=fmaf(z0.w,u.w,ca[0]);
            cb[0]=fmaf(z0.x,v.x,cb[0]); cb[0]=fmaf(z0.y,v.y,cb[0]);
            cb[0]=fmaf(z0.z,v.z,cb[0]); cb[0]=fmaf(z0.w,v.w,cb[0]);
            ca[1]=fmaf(z1.x,u.x,ca[1]); ca[1]=fmaf(z1.y,u.y,ca[1]);
            ca[1]=fmaf(z1.z,u.z,ca[1]); ca[1]=fmaf(z1.w,u.w,ca[1]);
            cb[1]=fmaf(z1.x,v.x,cb[1]); cb[1]=fmaf(z1.y,v.y,cb[1]);
            cb[1]=fmaf(z1.z,v.z,cb[1]); cb[1]=fmaf(z1.w,v.w,cb[1]);
            ca[2]=fmaf(z2.x,u.x,ca[2]); ca[2]=fmaf(z2.y,u.y,ca[2]);
            ca[2]=fmaf(z2.z,u.z,ca[2]); ca[2]=fmaf(z2.w,u.w,ca[2]);
            cb[2]=fmaf(z2.x,v.x,cb[2]); cb[2]=fmaf(z2.y,v.y,cb[2]);
            cb[2]=fmaf(z2.z,v.z,cb[2]); cb[2]=fmaf(z2.w,v.w,cb[2]);
            ca[3]=fmaf(z3.x,u.x,ca[3]); ca[3]=fmaf(z3.y,u.y,ca[3]);
            ca[3]=fmaf(z3.z,u.z,ca[3]); ca[3]=fmaf(z3.w,u.w,ca[3]);
            cb[3]=fmaf(z3.x,v.x,cb[3]); cb[3]=fmaf(z3.y,v.y,cb[3]);
            cb[3]=fmaf(z3.z,v.z,cb[3]); cb[3]=fmaf(z3.w,v.w,cb[3]);
        }
        #pragma unroll
        for (int p = 0; p < 4; ++p) {
            int slot = ty * 4 + p;
            float a = aa[slot];
            float dv0 = fmaf(-2.0f, ca[p], a + bk0);
            float dv1 = fmaf(-2.0f, cb[p], a + bk1);
            float m1 = dv0; int k1 = c0 + tx;
            if (dv1 < m1) { m1 = dv1; k1 = c0 + 32 + tx; }
            #pragma unroll
            for (int o = 16; o; o >>= 1) {
                float ov = __shfl_xor_sync(0xffffffffu, m1, o);
                int   ok = __shfl_xor_sync(0xffffffffu, k1, o);
                if (ov < m1 || (ov == m1 && ok < k1)) { m1 = ov; k1 = ok; }
            }
            if (tx == 0 && ns[slot] >= 0) {
                g_pm1[cy * NPOS + base + slot] = m1;
                g_pk1[cy * NPOS + base + slot] = k1;
            }
        }
        __syncthreads();
    }
}

__global__ void k_ex2() {
    int i = blockIdx.x * blockDim.x + threadIdx.x;
    if (i >= g_cnt) return;
    float m = FLT_MAX; int k = 0;
    #pragma unroll
    for (int cy = 0; cy < 16; ++cy) {
        float mm = g_pm1[cy * NPOS + i];
        int   kk = g_pk1[cy * NPOS + i];
        if (mm < m || (mm == m && kk < k)) { m = mm; k = kk; }
    }
    g_idx[g_flag[i]] = k;
}

// ---------------------------------------------------------------------------
// Output + loss (proven in R3)
// ---------------------------------------------------------------------------
__global__ void k_out(const float* __restrict__ z, const float* __restrict__ emb,
                      float* __restrict__ out) {
    const int nitems = NPOS * 64;
    float local = 0.f;
    for (int item = blockIdx.x * blockDim.x + threadIdx.x;
         item < nitems; item += gridDim.x * blockDim.x) {
        int n  = item & (NPOS - 1);
        int dq = item >> 16;
        int idx = __ldg(&g_idx[n]);
        float4 e4 = *(const float4*)(emb + (size_t)idx * DDIM + (dq << 2));
        int b = n >> 12, hw = n & 4095;
        size_t base = ((size_t)b << 20) + ((size_t)(dq << 2) << 12) + hw;
        float ev[4] = {e4.x, e4.y, e4.z, e4.w};
        #pragma unroll
        for (int q = 0; q < 4; ++q) {
            size_t a = base + ((size_t)q << 12);
            float zz = z[a];
            float diff = ev[q] - zz;
            out[a] = zz + diff;
            local = fmaf(diff, diff, local);
        }
    }
    #pragma unroll
    for (int o = 16; o; o >>= 1) local += __shfl_xor_sync(0xffffffffu, local, o);
    __shared__ float ws[32];
    int lane = threadIdx.x & 31, w = threadIdx.x >> 5;
    if (lane == 0) ws[w] = local;
    __syncthreads();
    if (w == 0) {
        float s = (lane < (int)(blockDim.x >> 5)) ? ws[lane] : 0.f;
        #pragma unroll
        for (int o = 16; o; o >>= 1) s += __shfl_xor_sync(0xffffffffu, s, o);
        if (lane == 0) atomicAdd(&g_loss, (double)s);
    }
}

__global__ void k_fin(float* __restrict__ out, long long out_size) {
    int i = blockIdx.x * blockDim.x + threadIdx.x;
    if (i < NPOS && (long long)ZQ_ELEMS + i < out_size)
        out[ZQ_ELEMS + i] = (float)g_idx[i];
    if (i == 0 && (long long)ZQ_ELEMS + NPOS < out_size)
        out[ZQ_ELEMS + NPOS] = (float)(0.25 * g_loss / (double)ZQ_ELEMS);
}

// ---------------------------------------------------------------------------
extern "C" void kernel_launch(void* const* d_in, const int* in_sizes, int n_in,
                              void* d_out, int out_size) {
    const float* z   = (const float*)d_in[0];
    const float* emb = (const float*)d_in[1];
    float* out = (float*)d_out;

    cudaFuncSetAttribute(k_mma, cudaFuncAttributeMaxDynamicSharedMemorySize, SM_TOTAL);
    cudaFuncSetAttribute(k_ex1, cudaFuncAttributeMaxDynamicSharedMemorySize, SMEX);

    k_prep<<<KCODE / 8, 256>>>(emb);
    k_mma<<<NPOS / 128, 256, SM_TOTAL>>>(z);
    k_gz<<<256, 256>>>(z);
    k_ex1<<<dim3(64, 16), 256, SMEX>>>(emb);   // capture slot #4 = k_ex1
    k_ex2<<<NPOS / 256, 256>>>();
    k_out<<<2048, 256>>>(z, emb, out);
    k_fin<<<(NPOS + 255) / 256, 256>>>(out, (long long)out_size);
}

// round 17
// speedup vs baseline: 1.0717x; 1.0451x over previous
#include <cuda_runtime.h>
#include <cuda_bf16.h>
#include <math.h>
#include <float.h>
#include <stdint.h>

// Problem constants
#define DDIM 256
#define KCODE 1024
#define HW 4096
#define NPOS 65536
#define ZQ_ELEMS 16777216

// Screening margin: dv_approx and dv_ref both lie on the ulp(~256)=3.05e-5
// grid; pre-rounding difference 2*eps_c ~ 3e-6 << ulp/2 => each rounds to
// within 1 grid point. gap > 2*ulp + slack => argmin provably identical.
#define DELTA_GAP 6.5e-5f

__device__ float  g_b[KCODE];
__device__ float  g_a[NPOS];
__device__ int    g_idx[NPOS];
__device__ int    g_flag[NPOS];
__device__ int    g_cnt;
__device__ double g_loss;
__device__ __align__(16) __nv_bfloat16 g_eh[KCODE * DDIM];
__device__ __align__(16) __nv_bfloat16 g_el[KCODE * DDIM];
__device__ __align__(16) float g_zf[(size_t)NPOS * DDIM / 8];
__device__ float g_pm1[16 * NPOS];
__device__ int   g_pk1[16 * NPOS];
// Per-k-half partial argmin state: [half][n]
__device__ float g_hm1[2 * NPOS];
__device__ float g_hm2[2 * NPOS];
__device__ int   g_hk1[2 * NPOS];

// ---------------------------------------------------------------------------
// PTX helpers — all sm_80-class features, valid on plain sm_103 target
// ---------------------------------------------------------------------------
__device__ __forceinline__ unsigned stu32(const void* p) {
    return (unsigned)__cvta_generic_to_shared(p);
}
__device__ __forceinline__ void cp16(unsigned dst, const void* src) {
    asm volatile("cp.async.cg.shared.global [%0], [%1], 16;" :: "r"(dst), "l"(src));
}
__device__ __forceinline__ void cp_commit() { asm volatile("cp.async.commit_group;"); }
__device__ __forceinline__ void cp_wait1()  { asm volatile("cp.async.wait_group 1;"); }
__device__ __forceinline__ void cp_wait0()  { asm volatile("cp.async.wait_group 0;"); }

__device__ __forceinline__ void ldm4(unsigned* r, unsigned addr) {
    asm volatile("ldmatrix.sync.aligned.m8n8.x4.shared.b16 {%0,%1,%2,%3}, [%4];"
        : "=r"(r[0]), "=r"(r[1]), "=r"(r[2]), "=r"(r[3]) : "r"(addr));
}
__device__ __forceinline__ void mma16816(float* c, const unsigned* a,
                                         unsigned b0, unsigned b1) {
    asm volatile(
        "mma.sync.aligned.m16n8k16.row.col.f32.bf16.bf16.f32 "
        "{%0,%1,%2,%3}, {%4,%5,%6,%7}, {%8,%9}, {%0,%1,%2,%3};"
        : "+f"(c[0]), "+f"(c[1]), "+f"(c[2]), "+f"(c[3])
        : "r"(a[0]), "r"(a[1]), "r"(a[2]), "r"(a[3]), "r"(b0), "r"(b1));
}

// ---------------------------------------------------------------------------
// emb prep (unchanged, proven)
// ---------------------------------------------------------------------------
__global__ void k_prep(const float* __restrict__ emb) {
    if (blockIdx.x == 0 && threadIdx.x == 0) { g_loss = 0.0; g_cnt = 0; }
    int warp = blockIdx.x * (blockDim.x >> 5) + (threadIdx.x >> 5);
    int lane = threadIdx.x & 31;
    if (warp >= KCODE) return;
    const float* row = emb + (size_t)warp * DDIM;
    float s = 0.f;
    #pragma unroll
    for (int d = lane; d < DDIM; d += 32) { float v = row[d]; s = fmaf(v, v, s); }
    #pragma unroll
    for (int o = 16; o; o >>= 1) s += __shfl_xor_sync(0xffffffffu, s, o);
    if (lane == 0) g_b[warp] = s;

    __align__(16) __nv_bfloat16 h[8], l[8];
    int base = lane * 8;
    #pragma unroll
    for (int q = 0; q < 8; ++q) {
        float v = row[base + q];
        h[q] = __float2bfloat16(v);
        l[q] = __float2bfloat16(v - __bfloat162float(h[q]));
    }
    *reinterpret_cast<uint4*>(&g_eh[warp * DDIM + base]) = *reinterpret_cast<uint4*>(h);
    *reinterpret_cast<uint4*>(&g_el[warp * DDIM + base]) = *reinterpret_cast<uint4*>(l);
}

// ---------------------------------------------------------------------------
// HMMA screening kernel: proven R14/R16 mainloop, now k-split across 2 CTAs
// per n-tile (1024 CTAs -> 6.92 waves, kills the 4-vs-3.46 wave quantization).
// CTA = 128 n x 512 codes (half = bid&1), NCH=16 chunks of 32 codes.
// Writes per-half (m1,m2,k1) partials; k_merge does the gap test.
// ---------------------------------------------------------------------------
#define ROWB 528
#define OFF_AH 0
#define OFF_AL 67584            /* 128*528 */
#define OFF_B  135168           /* 2 bufs x (Bh 16896 + Bl 16896); also z stage */
#define OFF_BS 202752           /* 512 floats (this half's b_k) */
#define OFF_AS 206848           /* 128 floats */
#define SM_TOTAL 207360
#define PSTG 132
#define NCH 16

extern __shared__ char sm_raw[];

__global__ void __launch_bounds__(256, 1)
k_mma(const float* __restrict__ z) {
    unsigned sb = stu32(sm_raw);
    const int tid = threadIdx.x;
    const int lane = tid & 31, w = tid >> 5;         // w = n-tile 0..7
    const int tile = blockIdx.x >> 1;
    const int half = blockIdx.x & 1;
    const int n0 = tile * 128;
    const int kbase = half << 9;                     // 0 or 512

    // ---------- Prologue: stage z (fp32) -> split into Ah/Al + exact a_n ----
    float* stg = (float*)(sm_raw + OFF_B);
    const int b = n0 >> 12, hw0 = n0 & 4095;
    const float* zb = z + ((size_t)b << 20) + hw0;
    float a_acc = 0.f;

    #pragma unroll
    for (int c = 0; c < 2; ++c) {
        for (int i = tid; i < 128 * 32; i += 256) {
            int d = i >> 5, j = i & 31;
            cp16(sb + OFF_B + d * ROWB + j * 16,
                 zb + (size_t)(c * 128 + d) * HW + j * 4);
        }
        cp_commit(); cp_wait0();
        __syncthreads();
        {
            int nn = tid >> 1, hf = tid & 1;
            unsigned dstA = (unsigned)(nn * ROWB + c * 256 + hf * 128);
            #pragma unroll
            for (int g = 0; g < 8; ++g) {
                __align__(16) __nv_bfloat16 hh[8], ll[8];
                #pragma unroll
                for (int q = 0; q < 8; ++q) {
                    float v = stg[(hf * 64 + g * 8 + q) * PSTG + nn];
                    hh[q] = __float2bfloat16(v);
                    ll[q] = __float2bfloat16(v - __bfloat162float(hh[q]));
                }
                *(uint4*)(sm_raw + OFF_AH + dstA + g * 16) = *(uint4*)hh;
                *(uint4*)(sm_raw + OFF_AL + dstA + g * 16) = *(uint4*)ll;
            }
        }
        if (tid < 128) {
            #pragma unroll 4
            for (int dl = 0; dl < 128; ++dl) {
                float v = stg[dl * PSTG + tid];
                a_acc = fmaf(v, v, a_acc);
            }
        }
        __syncthreads();
    }

    float* bsm  = (float*)(sm_raw + OFF_BS);         // this half's 512 b_k
    float* asm_ = (float*)(sm_raw + OFF_AS);
    if (tid < 128) {
        asm_[tid] = a_acc;
        if (half == 0) g_a[n0 + tid] = a_acc;
    }
    for (int i = tid; i < 512; i += 256) bsm[i] = g_b[kbase + i];

    auto prefB = [&](int c) {
        unsigned bufh = sb + OFF_B + (c & 1) * 33792;
        const char* eh = (const char*)g_eh;
        const char* el = (const char*)g_el;
        for (int u = tid; u < 32 * 32; u += 256) {
            int r = u >> 5, j = u & 31;
            size_t src = (size_t)(kbase + c * 32 + r) * 512 + j * 16;
            unsigned dst = r * ROWB + j * 16;
            cp16(bufh + dst, eh + src);
            cp16(bufh + 16896 + dst, el + src);
        }
    };
    prefB(0); cp_commit();
    prefB(1); cp_commit();
    __syncthreads();

    const int grp = lane >> 3, ii = lane & 7;
    const unsigned aOff = (unsigned)((w * 16 + ((grp & 1) ? 8 : 0) + ii) * ROWB
                                     + ((grp & 2) ? 16 : 0));
    const unsigned bOff = (unsigned)((((grp >> 1) ? 8 : 0) + ii) * ROWB
                                     + ((grp & 1) ? 16 : 0));

    const float aA = asm_[w * 16 + (lane >> 2)];
    const float aB = asm_[w * 16 + (lane >> 2) + 8];
    float m1A = FLT_MAX, m2A = FLT_MAX, m1B = FLT_MAX, m2B = FLT_MAX;
    int k1A = kbase, k1B = kbase;

    #define UPD(m1, m2, k1, dv, k) \
        { if ((dv) < (m1)) { (m2) = (m1); (m1) = (dv); (k1) = (k); } \
          else if ((dv) < (m2)) (m2) = (dv); }

    for (int c = 0; c < NCH; ++c) {
        if (c == NCH - 1) cp_wait0(); else cp_wait1();
        __syncthreads();

        unsigned bufh = sb + OFF_B + (c & 1) * 33792;
        unsigned pAh = sb + OFF_AH + aOff;
        unsigned pAl = sb + OFF_AL + aOff;
        unsigned pH0 = bufh + bOff;
        unsigned pH1 = bufh + 16 * ROWB + bOff;
        unsigned pL0 = bufh + 16896 + bOff;
        unsigned pL1 = bufh + 16896 + 16 * ROWB + bOff;

        float Ch[4][4], Cl[4][4];
        #pragma unroll
        for (int t = 0; t < 4; ++t)
            #pragma unroll
            for (int q = 0; q < 4; ++q) { Ch[t][q] = 0.f; Cl[t][q] = 0.f; }

        #pragma unroll 8
        for (int s = 0; s < 16; ++s) {
            unsigned Ah[4], Al[4], B0[4], B1[4], B2[4], B3[4];
            ldm4(Ah, pAh); ldm4(Al, pAl);
            ldm4(B0, pH0); ldm4(B1, pH1);
            ldm4(B2, pL0); ldm4(B3, pL1);
            mma16816(Cl[0], Ah, B2[0], B2[1]);   // zh*el
            mma16816(Cl[1], Ah, B2[2], B2[3]);
            mma16816(Cl[2], Ah, B3[0], B3[1]);
            mma16816(Cl[3], Ah, B3[2], B3[3]);
            mma16816(Ch[0], Ah, B0[0], B0[1]);   // zh*eh
            mma16816(Ch[1], Ah, B0[2], B0[3]);
            mma16816(Ch[2], Ah, B1[0], B1[1]);
            mma16816(Ch[3], Ah, B1[2], B1[3]);
            mma16816(Cl[0], Al, B0[0], B0[1]);   // zl*eh
            mma16816(Cl[1], Al, B0[2], B0[3]);
            mma16816(Cl[2], Al, B1[0], B1[1]);
            mma16816(Cl[3], Al, B1[2], B1[3]);
            pAh += 32; pAl += 32; pH0 += 32; pH1 += 32; pL0 += 32; pL1 += 32;
        }

        int kl = c * 32 + (lane & 3) * 2;        // local k within half
        #pragma unroll
        for (int t = 0; t < 4; ++t) {
            int kc = kl + t * 8;
            float b0 = bsm[kc], b1 = bsm[kc + 1];
            float d0 = fmaf(-2.f, Ch[t][0] + Cl[t][0], aA + b0);
            float d1 = fmaf(-2.f, Ch[t][1] + Cl[t][1], aA + b1);
            float d2 = fmaf(-2.f, Ch[t][2] + Cl[t][2], aB + b0);
            float d3 = fmaf(-2.f, Ch[t][3] + Cl[t][3], aB + b1);
            int kg = kbase + kc;
            UPD(m1A, m2A, k1A, d0, kg);
            UPD(m1A, m2A, k1A, d1, kg + 1);
            UPD(m1B, m2B, k1B, d2, kg);
            UPD(m1B, m2B, k1B, d3, kg + 1);
        }

        __syncthreads();
        if (c + 2 < NCH) { prefB(c + 2); cp_commit(); }
    }

    #pragma unroll
    for (int o = 1; o <= 2; o <<= 1) {
        float om1 = __shfl_xor_sync(0xffffffffu, m1A, o);
        int   ok1 = __shfl_xor_sync(0xffffffffu, k1A, o);
        float om2 = __shfl_xor_sync(0xffffffffu, m2A, o);
        bool take = (om1 < m1A) || (om1 == m1A && ok1 < k1A);
        m2A = fminf(fminf(m2A, om2), take ? m1A : om1);
        if (take) { m1A = om1; k1A = ok1; }

        om1 = __shfl_xor_sync(0xffffffffu, m1B, o);
        ok1 = __shfl_xor_sync(0xffffffffu, k1B, o);
        om2 = __shfl_xor_sync(0xffffffffu, m2B, o);
        take = (om1 < m1B) || (om1 == m1B && ok1 < k1B);
        m2B = fminf(fminf(m2B, om2), take ? m1B : om1);
        if (take) { m1B = om1; k1B = ok1; }
    }
    if ((lane & 3) == 0) {
        int nA = n0 + w * 16 + (lane >> 2);
        int sA = half * NPOS + nA;
        g_hm1[sA] = m1A; g_hm2[sA] = m2A; g_hk1[sA] = k1A;
        int sB = sA + 8;
        g_hm1[sB] = m1B; g_hm2[sB] = m2B; g_hk1[sB] = k1B;
    }
}

// ---------------------------------------------------------------------------
// Merge the two k-halves, gap test, flag ambiguous positions (R7 logic:
// half B's k strictly higher -> strict < keeps lowest-k tie-break).
// ---------------------------------------------------------------------------
__global__ void k_merge() {
    int n = blockIdx.x * blockDim.x + threadIdx.x;
    if (n >= NPOS) return;
    float m1a = g_hm1[n],        m2a = g_hm2[n];        int k1a = g_hk1[n];
    float m1b = g_hm1[NPOS + n], m2b = g_hm2[NPOS + n]; int k1b = g_hk1[NPOS + n];
    bool bwin = (m1b < m1a);
    float m1 = bwin ? m1b : m1a;
    int   k1 = bwin ? k1b : k1a;
    float m2 = fminf(fminf(m2a, m2b), bwin ? m1a : m1b);
    if (m2 - m1 > DELTA_GAP) g_idx[n] = k1;
    else g_flag[atomicAdd(&g_cnt, 1)] = n;
}

// ---------------------------------------------------------------------------
// One-shot z gather (R12, proven)
// ---------------------------------------------------------------------------
__global__ void k_gz(const float* __restrict__ z) {
    int cnt = g_cnt;
    int wg = blockIdx.x * (blockDim.x >> 5) + (threadIdx.x >> 5);
    int lane = threadIdx.x & 31;
    for (int s = wg; s < cnt; s += gridDim.x * (blockDim.x >> 5)) {
        int n = g_flag[s];
        const float* zp = z + ((size_t)(n >> 12) << 20) + (n & 4095);
        float* dst = g_zf + (size_t)s * DDIM;
        #pragma unroll
        for (int j = 0; j < 8; ++j) {
            int d = lane + 32 * j;
            dst[d] = __ldg(zp + ((size_t)d << 12));
        }
    }
}

// ---------------------------------------------------------------------------
// Exact fallback stage 1 (R14, proven, grid (32,16)): 4-pos register blocking.
// ---------------------------------------------------------------------------
#define EXP 260
#define SMEX ((64 * EXP + 32 * EXP) * 4)

extern __shared__ float exs[];

__global__ __launch_bounds__(256)
void k_ex1(const float* __restrict__ emb) {
    float* es = exs;                     // [64][EXP]
    float* zs = exs + 64 * EXP;          // [32][EXP]
    __shared__ int ns[32];
    __shared__ float aa[32];
    int tx = threadIdx.x & 31, ty = threadIdx.x >> 5;
    const int cy = blockIdx.y, c0 = cy * 64;
    const int cnt = g_cnt;
    if (cnt == 0) return;

    for (int i = threadIdx.x; i < 64 * 64; i += 256) {
        int r = i >> 6, q = (i & 63) << 2;
        *(float4*)(es + r * EXP + q) =
            *(const float4*)(emb + (size_t)(c0 + r) * DDIM + q);
    }
    float bk0 = g_b[c0 + tx], bk1 = g_b[c0 + 32 + tx];
    __syncthreads();

    for (int base = blockIdx.x * 32; base < cnt; base += 32 * 32) {
        if (threadIdx.x < 32) {
            int v = (base + threadIdx.x < cnt) ? g_flag[base + threadIdx.x] : -1;
            ns[threadIdx.x] = v;
            aa[threadIdx.x] = (v >= 0) ? g_a[v] : 0.f;
        }
        __syncthreads();
        for (int i = threadIdx.x; i < 32 * 64; i += 256) {
            int sl = i >> 6, q = (i & 63) << 2;
            float4 v = (base + sl < cnt)
                ? *(const float4*)(g_zf + (size_t)(base + sl) * DDIM + q)
                : make_float4(0.f, 0.f, 0.f, 0.f);
            *(float4*)(zs + sl * EXP + q) = v;
        }
        __syncthreads();

        float ca[4] = {0.f, 0.f, 0.f, 0.f}, cb[4] = {0.f, 0.f, 0.f, 0.f};
        const float* zr0 = zs + (ty * 4 + 0) * EXP;
        const float* zr1 = zs + (ty * 4 + 1) * EXP;
        const float* zr2 = zs + (ty * 4 + 2) * EXP;
        const float* zr3 = zs + (ty * 4 + 3) * EXP;
        const float* e0 = es + tx * EXP;
        const float* e1 = es + (tx + 32) * EXP;
        #pragma unroll 4
        for (int q = 0; q < 64; ++q) {
            float4 u = *(const float4*)(e0 + 4 * q);
            float4 v = *(const float4*)(e1 + 4 * q);
            float4 z0 = *(const float4*)(zr0 + 4 * q);
            float4 z1 = *(const float4*)(zr1 + 4 * q);
            float4 z2 = *(const float4*)(zr2 + 4 * q);
            float4 z3 = *(const float4*)(zr3 + 4 * q);
            ca[0]=fmaf(z0.x,u.x,ca[0]); ca[0]=fmaf(z0.y,u.y,ca[0]);
            ca[0]=fmaf(z0.z,u.z,ca[0]); ca[0]=fmaf(z0.w,u.w,ca[0]);
            cb[0]=fmaf(z0.x,v.x,cb[0]); cb[0]=fmaf(z0.y,v.y,cb[0]);
            cb[0]=fmaf(z0.z,v.z,cb[0]); cb[0]=fmaf(z0.w,v.w,cb[0]);
            ca[1]=fmaf(z1.x,u.x,ca[1]); ca[1]=fmaf(z1.y,u.y,ca[1]);
            ca[1]=fmaf(z1.z,u.z,ca[1]); ca[1]=fmaf(z1.w,u.w,ca[1]);
            cb[1]=fmaf(z1.x,v.x,cb[1]); cb[1]=fmaf(z1.y,v.y,cb[1]);
            cb[1]=fmaf(z1.z,v.z,cb[1]); cb[1]=fmaf(z1.w,v.w,cb[1]);
            ca[2]=fmaf(z2.x,u.x,ca[2]); ca[2]=fmaf(z2.y,u.y,ca[2]);
            ca[2]=fmaf(z2.z,u.z,ca[2]); ca[2]=fmaf(z2.w,u.w,ca[2]);
            cb[2]=fmaf(z2.x,v.x,cb[2]); cb[2]=fmaf(z2.y,v.y,cb[2]);
            cb[2]=fmaf(z2.z,v.z,cb[2]); cb[2]=fmaf(z2.w,v.w,cb[2]);
            ca[3]=fmaf(z3.x,u.x,ca[3]); ca[3]=fmaf(z3.y,u.y,ca[3]);
            ca[3]=fmaf(z3.z,u.z,ca[3]); ca[3]=fmaf(z3.w,u.w,ca[3]);
            cb[3]=fmaf(z3.x,v.x,cb[3]); cb[3]=fmaf(z3.y,v.y,cb[3]);
            cb[3]=fmaf(z3.z,v.z,cb[3]); cb[3]=fmaf(z3.w,v.w,cb[3]);
        }
        #pragma unroll
        for (int p = 0; p < 4; ++p) {
            int slot = ty * 4 + p;
            float a = aa[slot];
            float dv0 = fmaf(-2.0f, ca[p], a + bk0);
            float dv1 = fmaf(-2.0f, cb[p], a + bk1);
            float m1 = dv0; int k1 = c0 + tx;
            if (dv1 < m1) { m1 = dv1; k1 = c0 + 32 + tx; }
            #pragma unroll
            for (int o = 16; o; o >>= 1) {
                float ov = __shfl_xor_sync(0xffffffffu, m1, o);
                int   ok = __shfl_xor_sync(0xffffffffu, k1, o);
                if (ov < m1 || (ov == m1 && ok < k1)) { m1 = ov; k1 = ok; }
            }
            if (tx == 0 && ns[slot] >= 0) {
                g_pm1[cy * NPOS + base + slot] = m1;
                g_pk1[cy * NPOS + base + slot] = k1;
            }
        }
        __syncthreads();
    }
}

__global__ void k_ex2() {
    int i = blockIdx.x * blockDim.x + threadIdx.x;
    if (i >= g_cnt) return;
    float m = FLT_MAX; int k = 0;
    #pragma unroll
    for (int cy = 0; cy < 16; ++cy) {
        float mm = g_pm1[cy * NPOS + i];
        int   kk = g_pk1[cy * NPOS + i];
        if (mm < m || (mm == m && kk < k)) { m = mm; k = kk; }
    }
    g_idx[g_flag[i]] = k;
}

// ---------------------------------------------------------------------------
// Output + loss (proven in R3)
// ---------------------------------------------------------------------------
__global__ void k_out(const float* __restrict__ z, const float* __restrict__ emb,
                      float* __restrict__ out) {
    const int nitems = NPOS * 64;
    float local = 0.f;
    for (int item = blockIdx.x * blockDim.x + threadIdx.x;
         item < nitems; item += gridDim.x * blockDim.x) {
        int n  = item & (NPOS - 1);
        int dq = item >> 16;
        int idx = __ldg(&g_idx[n]);
        float4 e4 = *(const float4*)(emb + (size_t)idx * DDIM + (dq << 2));
        int b = n >> 12, hw = n & 4095;
        size_t base = ((size_t)b << 20) + ((size_t)(dq << 2) << 12) + hw;
        float ev[4] = {e4.x, e4.y, e4.z, e4.w};
        #pragma unroll
        for (int q = 0; q < 4; ++q) {
            size_t a = base + ((size_t)q << 12);
            float zz = z[a];
            float diff = ev[q] - zz;
            out[a] = zz + diff;
            local = fmaf(diff, diff, local);
        }
    }
    #pragma unroll
    for (int o = 16; o; o >>= 1) local += __shfl_xor_sync(0xffffffffu, local, o);
    __shared__ float ws[32];
    int lane = threadIdx.x & 31, w = threadIdx.x >> 5;
    if (lane == 0) ws[w] = local;
    __syncthreads();
    if (w == 0) {
        float s = (lane < (int)(blockDim.x >> 5)) ? ws[lane] : 0.f;
        #pragma unroll
        for (int o = 16; o; o >>= 1) s += __shfl_xor_sync(0xffffffffu, s, o);
        if (lane == 0) atomicAdd(&g_loss, (double)s);
    }
}

__global__ void k_fin(float* __restrict__ out, long long out_size) {
    int i = blockIdx.x * blockDim.x + threadIdx.x;
    if (i < NPOS && (long long)ZQ_ELEMS + i < out_size)
        out[ZQ_ELEMS + i] = (float)g_idx[i];
    if (i == 0 && (long long)ZQ_ELEMS + NPOS < out_size)
        out[ZQ_ELEMS + NPOS] = (float)(0.25 * g_loss / (double)ZQ_ELEMS);
}

// ---------------------------------------------------------------------------
extern "C" void kernel_launch(void* const* d_in, const int* in_sizes, int n_in,
                              void* d_out, int out_size) {
    const float* z   = (const float*)d_in[0];
    const float* emb = (const float*)d_in[1];
    float* out = (float*)d_out;

    cudaFuncSetAttribute(k_mma, cudaFuncAttributeMaxDynamicSharedMemorySize, SM_TOTAL);
    cudaFuncSetAttribute(k_ex1, cudaFuncAttributeMaxDynamicSharedMemorySize, SMEX);

    k_prep<<<KCODE / 8, 256>>>(emb);
    k_mma<<<(NPOS / 128) * 2, 256, SM_TOTAL>>>(z);
    k_merge<<<NPOS / 256, 256>>>();
    k_gz<<<256, 256>>>(z);                       // capture slot #4
    k_ex1<<<dim3(32, 16), 256, SMEX>>>(emb);
    k_ex2<<<NPOS / 256, 256>>>();
    k_out<<<2048, 256>>>(z, emb, out);
    k_fin<<<(NPOS + 255) / 256, 256>>>(out, (long long)out_size);
}